// round 10
// baseline (speedup 1.0000x reference)
#include <cuda_runtime.h>
#include <math.h>
#include <cstdint>

#define B_ 4
#define S_ 2048
#define D_ 1024
#define H_ 16
#define DK_ 64

// Scratch: device globals (no allocation allowed anywhere)
__device__ float g_Q[(size_t)B_ * S_ * D_];
__device__ float g_K[(size_t)B_ * S_ * D_];
__device__ float g_V[(size_t)B_ * S_ * D_];
__device__ float g_att[(size_t)B_ * S_ * D_];

__device__ __forceinline__ uint32_t f2tf32(float f) {
    uint32_t u;
    asm("cvt.rna.tf32.f32 %0, %1;" : "=r"(u) : "f"(f));
    return u;
}

__device__ __forceinline__ float ex2(float x) {
    float y;
    asm("ex2.approx.ftz.f32 %0, %1;" : "=f"(y) : "f"(x));
    return y;
}

__device__ __forceinline__ void mma_tf32(float* d, const uint32_t* a, const uint32_t* b) {
    asm volatile(
        "mma.sync.aligned.m16n8k8.row.col.f32.tf32.tf32.f32 "
        "{%0,%1,%2,%3}, {%4,%5,%6,%7}, {%8,%9}, {%0,%1,%2,%3};\n"
        : "+f"(d[0]), "+f"(d[1]), "+f"(d[2]), "+f"(d[3])
        : "r"(a[0]), "r"(a[1]), "r"(a[2]), "r"(a[3]), "r"(b[0]), "r"(b[1]));
}

// ldmatrix x4 (b16 tiles; tf32 data is opaque bits).
__device__ __forceinline__ void ldsm_x4(uint32_t* r, uint32_t saddr) {
    asm volatile("ldmatrix.sync.aligned.m8n8.x4.shared.b16 {%0,%1,%2,%3}, [%4];"
        : "=r"(r[0]), "=r"(r[1]), "=r"(r[2]), "=r"(r[3]) : "r"(saddr));
}

__device__ __forceinline__ uint32_t s2u(const void* p) {
    return (uint32_t)__cvta_generic_to_shared(p);
}

// ---------------------------------------------------------------------------
// GEMM body: C[M,N] = A[M,K] @ B[N,K]^T + bias[N], tf32 mma.sync.
// CTA tile 128x256, k-chunk 32, 256 threads (8 warps in 2x4), warp tile 64x64.
// tf32 conversion once per element at staging; fragments via ldmatrix.
// ---------------------------------------------------------------------------
#define TCM 128
#define TCN 256

__device__ __forceinline__ void gemm_body(
    const float* __restrict__ A, const float* __restrict__ Bm,
    const float* __restrict__ bias, float* __restrict__ C,
    int N, int K, int m0, int n0)
{
    extern __shared__ uint32_t smu[];
    uint32_t* As = smu;              // [128][36]
    uint32_t* Bs = smu + 128 * 36;   // [256][36]

    const int tid = threadIdx.x;
    const int lane = tid & 31, warp = tid >> 5;
    const int wr = warp >> 2, wc = warp & 3;     // 2 x 4 warp grid
    const int l4 = lane >> 2, lm = lane & 3;

    const int cr = tid >> 3;          // 0..31
    const int cc = (tid & 7) * 4;     // 0..28

    const float* Ap = A + (size_t)(m0 + cr) * K + cc;
    const float* Bp = Bm + (size_t)(n0 + cr) * K + cc;

    // ldmatrix per-lane base byte offsets
    const uint32_t a_u = s2u(As) + 4u * ((wr * 64 + (lane & 15)) * 36 + (lane >> 4) * 4);
    const uint32_t b_u = s2u(Bs) + 4u * ((wc * 64 + (lane & 7) + (lane >> 4) * 8) * 36
                                         + ((lane >> 3) & 1) * 4);

    float acc[4][8][4];
#pragma unroll
    for (int i = 0; i < 4; i++)
#pragma unroll
        for (int j = 0; j < 8; j++)
#pragma unroll
            for (int t = 0; t < 4; t++) acc[i][j][t] = 0.f;

    const int nk = K >> 5;

    float4 sa[4], sb[8];
#pragma unroll
    for (int i = 0; i < 4; i++)
        sa[i] = *(const float4*)(Ap + (size_t)(32 * i) * K);
#pragma unroll
    for (int i = 0; i < 8; i++)
        sb[i] = *(const float4*)(Bp + (size_t)(32 * i) * K);

    for (int kt = 0; kt < nk; kt++) {
        // store staged tile (convert to tf32 once per element)
#pragma unroll
        for (int i = 0; i < 4; i++) {
            uint4 ua = {f2tf32(sa[i].x), f2tf32(sa[i].y), f2tf32(sa[i].z), f2tf32(sa[i].w)};
            *(uint4*)&As[(cr + 32 * i) * 36 + cc] = ua;
        }
#pragma unroll
        for (int i = 0; i < 8; i++) {
            uint4 ub = {f2tf32(sb[i].x), f2tf32(sb[i].y), f2tf32(sb[i].z), f2tf32(sb[i].w)};
            *(uint4*)&Bs[(cr + 32 * i) * 36 + cc] = ub;
        }
        __syncthreads();

        // prefetch next tile into registers (overlaps with MMA below)
        if (kt + 1 < nk) {
            const int ko = (kt + 1) * 32;
#pragma unroll
            for (int i = 0; i < 4; i++)
                sa[i] = *(const float4*)(Ap + (size_t)(32 * i) * K + ko);
#pragma unroll
            for (int i = 0; i < 8; i++)
                sb[i] = *(const float4*)(Bp + (size_t)(32 * i) * K + ko);
        }

#pragma unroll
        for (int ks = 0; ks < 4; ks++) {
            uint32_t af[4][4], bf[4][4];
#pragma unroll
            for (int mt = 0; mt < 4; mt++)
                ldsm_x4(af[mt], a_u + mt * (16 * 36 * 4) + ks * 32);
#pragma unroll
            for (int np = 0; np < 4; np++)
                ldsm_x4(bf[np], b_u + np * (16 * 36 * 4) + ks * 32);
#pragma unroll
            for (int mt = 0; mt < 4; mt++)
#pragma unroll
                for (int np = 0; np < 4; np++) {
                    mma_tf32(acc[mt][2 * np],     af[mt], bf[np]);
                    mma_tf32(acc[mt][2 * np + 1], af[mt], bf[np] + 2);
                }
        }
        __syncthreads();
    }

    // epilogue with bias
#pragma unroll
    for (int mt = 0; mt < 4; mt++) {
        const int r = m0 + wr * 64 + mt * 16 + l4;
#pragma unroll
        for (int nt = 0; nt < 8; nt++) {
            const int c = n0 + wc * 64 + nt * 8 + 2 * lm;
            const float2 b2 = *(const float2*)&bias[c];
            float2 v0 = {acc[mt][nt][0] + b2.x, acc[mt][nt][1] + b2.y};
            float2 v1 = {acc[mt][nt][2] + b2.x, acc[mt][nt][3] + b2.y};
            *(float2*)&C[(size_t)r * N + c] = v0;
            *(float2*)&C[(size_t)(r + 8) * N + c] = v1;
        }
    }
}

// Fused Q/K/V projection: blockIdx.z selects which projection.
__global__ void __launch_bounds__(256) gemm_qkv(
    const float* __restrict__ q, const float* __restrict__ k, const float* __restrict__ v,
    const float* __restrict__ Wq, const float* __restrict__ Wk, const float* __restrict__ Wv,
    const float* __restrict__ bq, const float* __restrict__ bk, const float* __restrict__ bv,
    float* __restrict__ oq, float* __restrict__ ok, float* __restrict__ ov)
{
    const int z = blockIdx.z;
    const float* A = (z == 0) ? q : (z == 1) ? k : v;
    const float* W = (z == 0) ? Wq : (z == 1) ? Wk : Wv;
    const float* bias = (z == 0) ? bq : (z == 1) ? bk : bv;
    float* C = (z == 0) ? oq : (z == 1) ? ok : ov;
    gemm_body(A, W, bias, C, D_, D_, blockIdx.y * TCM, blockIdx.x * TCN);
}

__global__ void __launch_bounds__(256) gemm_single(
    const float* __restrict__ A, const float* __restrict__ W,
    const float* __restrict__ bias, float* __restrict__ C)
{
    gemm_body(A, W, bias, C, D_, D_, blockIdx.y * TCM, blockIdx.x * TCN);
}

// ---------------------------------------------------------------------------
// Flash attention, tf32 mma.sync. CTA = 128 q-rows, 256 threads (8 warps x 16
// rows). 64-key tiles. Q fragments register-resident. K, V and P fragments all
// via conflict-free ldmatrix. V stored transposed (Vt[d][k], stride 68) via an
// in-register 4x4 quad shuffle transpose so stores stay coalesced.
// ---------------------------------------------------------------------------
__global__ void __launch_bounds__(256) attn_tf32(
    const float* __restrict__ Qg, const float* __restrict__ Kg,
    const float* __restrict__ Vg, float* __restrict__ Og)
{
    extern __shared__ float sm[];
    float* QP = sm;                 // [128][68] : Q staging, then P (per-warp rows)
    float* Ks = QP + 128 * 68;      // [64][68]   K[n][k]
    float* Vt = Ks + 64 * 68;       // [64][68]   V^T : Vt[d][k]

    const int qt = blockIdx.x, h = blockIdx.y, b = blockIdx.z;
    const int tid = threadIdx.x, lane = tid & 31, warp = tid >> 5;
    const int l4 = lane >> 2, lm = lane & 3;
    const int q0 = qt * 128;

    const float* Qb = Qg + (size_t)b * S_ * D_ + h * DK_;
    const float* Kb = Kg + (size_t)b * S_ * D_ + h * DK_;
    const float* Vb = Vg + (size_t)b * S_ * D_ + h * DK_;

    // Load Q tile (convert to tf32 bits)
    {
        const int rr = tid >> 4, c4 = (tid & 15) * 4;
#pragma unroll
        for (int j = 0; j < 8; j++) {
            const int r = rr + j * 16;
            const float4 v = *(const float4*)&Qb[(size_t)(q0 + r) * D_ + c4];
            QP[r * 68 + c4 + 0] = __uint_as_float(f2tf32(v.x));
            QP[r * 68 + c4 + 1] = __uint_as_float(f2tf32(v.y));
            QP[r * 68 + c4 + 2] = __uint_as_float(f2tf32(v.z));
            QP[r * 68 + c4 + 3] = __uint_as_float(f2tf32(v.w));
        }
    }
    __syncthreads();

    // Extract Q fragments via ldmatrix (warp reads its own 16 rows)
    uint32_t qf[8][4];
    {
        const uint32_t q_u = s2u(QP) + 4u * ((warp * 16 + (lane & 15)) * 68 + (lane >> 4) * 4);
#pragma unroll
        for (int ks = 0; ks < 8; ks++)
            ldsm_x4(qf[ks], q_u + ks * 32);
    }
    __syncthreads();   // everyone done reading QP before P overwrites it

    // ldmatrix base offsets (K path and V path share the pattern; stride 68)
    const uint32_t k_u = s2u(Ks) + 4u * (((lane & 7) + (lane >> 4) * 8) * 68
                                         + ((lane >> 3) & 1) * 4);
    const uint32_t v_u = s2u(Vt) + 4u * (((lane & 7) + (lane >> 4) * 8) * 68
                                         + ((lane >> 3) & 1) * 4);
    const uint32_t p_u = s2u(QP + warp * 16 * 68)
                       + 4u * ((lane & 15) * 68 + (lane >> 4) * 4);

    float m0r = -1e30f, m1r = -1e30f, l0r = 0.f, l1r = 0.f;
    float o[8][4];
#pragma unroll
    for (int nt = 0; nt < 8; nt++)
#pragma unroll
        for (int i = 0; i < 4; i++) o[nt][i] = 0.f;

    float* Pw = QP + warp * 16 * 68;
    const int qr_lo = q0 + warp * 16;
    const int qr_hi = qr_lo + 15;
    const int nkb = 2 * qt + 2;

    const float SC2 = 0.125f * 1.4426950408889634f;

    for (int kb = 0; kb < nkb; kb++) {
        const int k0 = kb * 64;
        __syncthreads();
        // K tile load (row-major, tf32)
        {
            const int rr = tid >> 4, c4 = (tid & 15) * 4;
#pragma unroll
            for (int j = 0; j < 4; j++) {
                const int r = rr + j * 16;
                const float4 kv = *(const float4*)&Kb[(size_t)(k0 + r) * D_ + c4];
                Ks[r * 68 + c4 + 0] = __uint_as_float(f2tf32(kv.x));
                Ks[r * 68 + c4 + 1] = __uint_as_float(f2tf32(kv.y));
                Ks[r * 68 + c4 + 2] = __uint_as_float(f2tf32(kv.z));
                Ks[r * 68 + c4 + 3] = __uint_as_float(f2tf32(kv.w));
            }
        }
        // V tile load, transposed in registers (quad 4x4 shuffle transpose).
        // Quad lanes m=0..3 each load V[k=kg*4+m][d0..d0+3]; after the
        // transpose lane m holds column d0+m as a float4 along k.
        {
            const int m = lane & 3;
            const int dq = (lane >> 2) * 4;          // 0,4,...,28
#pragma unroll
            for (int j = 0; j < 4; j++) {
                const int kg = warp * 2 + (j >> 1);  // 0..15
                const int d0 = (j & 1) * 32 + dq;    // 0..60
                const int kk = k0 + kg * 4 + m;
                const float4 vv = *(const float4*)&Vb[(size_t)kk * D_ + d0];
                float4 mv;
                mv.x = __uint_as_float(f2tf32(vv.x));
                mv.y = __uint_as_float(f2tf32(vv.y));
                mv.z = __uint_as_float(f2tf32(vv.z));
                mv.w = __uint_as_float(f2tf32(vv.w));
                // round 1 (xor 1)
                float ox = __shfl_xor_sync(0xffffffffu, mv.x, 1);
                float oy = __shfl_xor_sync(0xffffffffu, mv.y, 1);
                float oz = __shfl_xor_sync(0xffffffffu, mv.z, 1);
                float ow = __shfl_xor_sync(0xffffffffu, mv.w, 1);
                float4 bq;
                if ((lane & 1) == 0) bq = make_float4(mv.x, ox, mv.z, oz);
                else                 bq = make_float4(oy, mv.y, ow, mv.w);
                // round 2 (xor 2)
                float px = __shfl_xor_sync(0xffffffffu, bq.x, 2);
                float py = __shfl_xor_sync(0xffffffffu, bq.y, 2);
                float pz = __shfl_xor_sync(0xffffffffu, bq.z, 2);
                float pw = __shfl_xor_sync(0xffffffffu, bq.w, 2);
                float4 tq;
                if ((lane & 2) == 0) tq = make_float4(bq.x, bq.y, px, py);
                else                 tq = make_float4(pz, pw, bq.z, bq.w);
                *(float4*)&Vt[(d0 + m) * 68 + kg * 4] = tq;
            }
        }
        __syncthreads();
        if (k0 > qr_hi) continue;   // whole tile masked for this warp (uniform)

        // S = Q @ K^T   (K b-frags via ldmatrix: np pair covers nt=2np,2np+1)
        float s[8][4];
#pragma unroll
        for (int nt = 0; nt < 8; nt++)
#pragma unroll
            for (int i = 0; i < 4; i++) s[nt][i] = 0.f;
#pragma unroll
        for (int ks = 0; ks < 8; ks++) {
#pragma unroll
            for (int np = 0; np < 4; np++) {
                uint32_t bb[4];
                ldsm_x4(bb, k_u + np * (16 * 68 * 4) + ks * 32);
                mma_tf32(s[2 * np],     qf[ks], bb);
                mma_tf32(s[2 * np + 1], qf[ks], bb + 2);
            }
        }

        // scale (log2 domain) + causal mask
        const bool full = (k0 + 63) <= qr_lo;
        const int r0g = qr_lo + l4, r1g = r0g + 8;
#pragma unroll
        for (int nt = 0; nt < 8; nt++) {
#pragma unroll
            for (int i = 0; i < 4; i++) s[nt][i] *= SC2;
            if (!full) {
                const int c = k0 + nt * 8 + 2 * lm;
                if (c     > r0g) s[nt][0] = -1e30f;
                if (c + 1 > r0g) s[nt][1] = -1e30f;
                if (c     > r1g) s[nt][2] = -1e30f;
                if (c + 1 > r1g) s[nt][3] = -1e30f;
            }
        }

        // online softmax (rows r0g: regs 0,1 / r1g: regs 2,3); quad reduction
        float mx0 = -1e30f, mx1 = -1e30f;
#pragma unroll
        for (int nt = 0; nt < 8; nt++) {
            mx0 = fmaxf(mx0, fmaxf(s[nt][0], s[nt][1]));
            mx1 = fmaxf(mx1, fmaxf(s[nt][2], s[nt][3]));
        }
        mx0 = fmaxf(mx0, __shfl_xor_sync(0xffffffffu, mx0, 1));
        mx0 = fmaxf(mx0, __shfl_xor_sync(0xffffffffu, mx0, 2));
        mx1 = fmaxf(mx1, __shfl_xor_sync(0xffffffffu, mx1, 1));
        mx1 = fmaxf(mx1, __shfl_xor_sync(0xffffffffu, mx1, 2));
        const float mn0 = fmaxf(m0r, mx0), mn1 = fmaxf(m1r, mx1);
        const float a0 = ex2(m0r - mn0), a1 = ex2(m1r - mn1);
        m0r = mn0; m1r = mn1;
        float sum0 = 0.f, sum1 = 0.f;
#pragma unroll
        for (int nt = 0; nt < 8; nt++) {
            s[nt][0] = ex2(s[nt][0] - mn0); sum0 += s[nt][0];
            s[nt][1] = ex2(s[nt][1] - mn0); sum0 += s[nt][1];
            s[nt][2] = ex2(s[nt][2] - mn1); sum1 += s[nt][2];
            s[nt][3] = ex2(s[nt][3] - mn1); sum1 += s[nt][3];
        }
        sum0 += __shfl_xor_sync(0xffffffffu, sum0, 1);
        sum0 += __shfl_xor_sync(0xffffffffu, sum0, 2);
        sum1 += __shfl_xor_sync(0xffffffffu, sum1, 1);
        sum1 += __shfl_xor_sync(0xffffffffu, sum1, 2);
        l0r = l0r * a0 + sum0;
        l1r = l1r * a1 + sum1;
#pragma unroll
        for (int nt = 0; nt < 8; nt++) {
            o[nt][0] *= a0; o[nt][1] *= a0;
            o[nt][2] *= a1; o[nt][3] *= a1;
        }

        // store P (tf32) into per-warp region
#pragma unroll
        for (int nt = 0; nt < 8; nt++) {
            const int c = nt * 8 + 2 * lm;
            float2 p0 = {__uint_as_float(f2tf32(s[nt][0])), __uint_as_float(f2tf32(s[nt][1]))};
            float2 p1 = {__uint_as_float(f2tf32(s[nt][2])), __uint_as_float(f2tf32(s[nt][3]))};
            *(float2*)&Pw[l4 * 68 + c]       = p0;
            *(float2*)&Pw[(l4 + 8) * 68 + c] = p1;
        }
        __syncwarp();

        // O += P @ V   (P a-frags + V b-frags via ldmatrix, all conflict-free)
#pragma unroll
        for (int ks = 0; ks < 8; ks++) {
            uint32_t pa[4];
            ldsm_x4(pa, p_u + ks * 32);
#pragma unroll
            for (int np = 0; np < 4; np++) {
                uint32_t bb[4];
                ldsm_x4(bb, v_u + np * (16 * 68 * 4) + ks * 32);
                mma_tf32(o[2 * np],     pa, bb);
                mma_tf32(o[2 * np + 1], pa, bb + 2);
            }
        }
    }

    // epilogue: normalize and store
    const float inv0 = 1.f / l0r, inv1 = 1.f / l1r;
    float* Ob = Og + (size_t)b * S_ * D_ + h * DK_;
    const int r0g = q0 + warp * 16 + l4, r1g = r0g + 8;
#pragma unroll
    for (int nt = 0; nt < 8; nt++) {
        const int c = nt * 8 + 2 * lm;
        float2 v0 = {o[nt][0] * inv0, o[nt][1] * inv0};
        float2 v1 = {o[nt][2] * inv1, o[nt][3] * inv1};
        *(float2*)&Ob[(size_t)r0g * D_ + c] = v0;
        *(float2*)&Ob[(size_t)r1g * D_ + c] = v1;
    }
}

// ---------------------------------------------------------------------------
extern "C" void kernel_launch(void* const* d_in, const int* in_sizes, int n_in,
                              void* d_out, int out_size)
{
    const float* q  = (const float*)d_in[0];
    const float* k  = (const float*)d_in[1];
    const float* v  = (const float*)d_in[2];
    const float* Wq = (const float*)d_in[3];
    const float* bq = (const float*)d_in[4];
    const float* Wk = (const float*)d_in[5];
    const float* bk = (const float*)d_in[6];
    const float* Wv = (const float*)d_in[7];
    const float* bv = (const float*)d_in[8];
    const float* Wo = (const float*)d_in[9];
    const float* bo = (const float*)d_in[10];
    // d_in[11] = causal mask (computed analytically, unused)
    float* out = (float*)d_out;

    float *pQ, *pK, *pV, *pA;
    cudaGetSymbolAddress((void**)&pQ, g_Q);
    cudaGetSymbolAddress((void**)&pK, g_K);
    cudaGetSymbolAddress((void**)&pV, g_V);
    cudaGetSymbolAddress((void**)&pA, g_att);

    const int M = B_ * S_;  // 8192
    const int gemm_smem = (128 + 256) * 36 * (int)sizeof(uint32_t);   // 55296
    const int attn_smem = (128 + 64 + 64) * 68 * (int)sizeof(float);  // 69632

    cudaFuncSetAttribute(gemm_qkv, cudaFuncAttributeMaxDynamicSharedMemorySize, gemm_smem);
    cudaFuncSetAttribute(gemm_single, cudaFuncAttributeMaxDynamicSharedMemorySize, gemm_smem);
    cudaFuncSetAttribute(attn_tf32, cudaFuncAttributeMaxDynamicSharedMemorySize, attn_smem);

    dim3 blk(256);
    dim3 gqkv(D_ / TCN, M / TCM, 3);  // (4, 64, 3)

    gemm_qkv<<<gqkv, blk, gemm_smem>>>(q, k, v, Wq, Wk, Wv, bq, bk, bv, pQ, pK, pV);

    dim3 gatt(S_ / 128, H_, B_);
    attn_tf32<<<gatt, blk, attn_smem>>>(pQ, pK, pV, pA);

    dim3 gproj(D_ / TCN, M / TCM);  // (4, 64)
    gemm_single<<<gproj, blk, gemm_smem>>>(pA, Wo, bo, out);
}